// round 13
// baseline (speedup 1.0000x reference)
#include <cuda_runtime.h>
#include <math.h>

// BoundaryLoss fully-fused kernel: persistent CTAs (one wave, grid-stride),
// 4 pixels/thread, scalar pairwise Sobel (8 border candidates), compile-time
// H/W/C, streaming (__ldcs) logit loop + cached (__ldg) target gather,
// last-block-done reduction.
// inputs: d_in[0] = logits (B,C,H,W) float32, d_in[1] = targets (B,H,W) int32
// output: scalar float32 mean of (nll * boundary_weight)

#define MAX_BLOCKS 8192
#define NUM_SMS 148
#define BLOCKS_PER_SM 5
__device__ double g_part[MAX_BLOCKS];
__device__ unsigned int g_count = 0;
__device__ double g_acc;   // generic fallback path

__global__ void zero_acc_kernel() { g_acc = 0.0; }
__global__ void finalize_acc_kernel(float* out, double inv_n) {
    out[0] = (float)(g_acc * inv_n);
}

// weight = exp(clip(sqrt(m2)*3, 0, 5)); integer m2 saturates at 3 =>
// only 4 distinct values.
__device__ __forceinline__ float weight_lut(int m2) {
    // exp(3)=20.0855370, exp(3*sqrt(2))=69.5913868, exp(5)=148.4131591
    return (m2 == 0) ? 1.0f
         : (m2 == 1) ? 20.0855370f
         : (m2 == 2) ? 69.5913868f
                     : 148.4131591f;
}

// max over candidate classes of gx^2+gy^2 for one 3x3 window.
// Candidates: the 8 border cells only (center has zero Sobel coefficient,
// so a class present only at the center has zero gradient).
__device__ __forceinline__ int boundary_m2(const int lab[9]) {
    // sobel_x = [-1 0 1; -2 0 2; -1 0 1], sobel_y = [-1 -2 -1; 0 0 0; 1 2 1]
    int maxm2 = 0;
    #pragma unroll
    for (int ii = 0; ii < 8; ii++) {
        int i = (ii < 4) ? ii : ii + 1;   // skip center (index 4)
        int c = lab[i];
        int gx = (lab[2] == c) + (lab[8] == c) - (lab[0] == c) - (lab[6] == c)
               + 2 * ((lab[5] == c) - (lab[3] == c));
        int gy = (lab[6] == c) + (lab[8] == c) - (lab[0] == c) - (lab[2] == c)
               + 2 * ((lab[7] == c) - (lab[1] == c));
        maxm2 = max(maxm2, gx * gx + gy * gy);
    }
    return maxm2;
}

template <int C, int H, int W>
__global__ __launch_bounds__(256, BLOCKS_PER_SM)
void boundary_loss_fused_kernel(const float* __restrict__ logits,
                                const int*   __restrict__ targets,
                                float* __restrict__ out,
                                int B, double inv_n) {
    constexpr int HW = H * W;
    constexpr int W4 = W >> 2;             // float4 groups per row
    const int Nq = B * H * W4;             // total quads

    float val = 0.0f;

    // ---- persistent grid-stride loop over quads ----
    for (int idx = blockIdx.x * blockDim.x + threadIdx.x;
         idx < Nq;
         idx += gridDim.x * blockDim.x) {

        int q  = idx % W4;
        int y  = (idx / W4) % H;
        int b  = idx / (W4 * H);
        int x4 = q << 2;

        // ---- label window: 3 rows x 6 cols (x4-1 .. x4+4), replicate padding ----
        int w6[3][6];
        #pragma unroll
        for (int r = 0; r < 3; r++) {
            int yy = min(max(y + r - 1, 0), H - 1);
            const int* trow = targets + (b * H + yy) * W;
            int4 c4 = __ldg((const int4*)(trow + x4));
            w6[r][1] = c4.x; w6[r][2] = c4.y; w6[r][3] = c4.z; w6[r][4] = c4.w;
            w6[r][0] = __ldg(trow + max(x4 - 1, 0));
            w6[r][5] = __ldg(trow + min(x4 + 4, W - 1));
        }

        // ---- boundary weights for the 4 pixels ----
        float wgt[4];
        #pragma unroll
        for (int i = 0; i < 4; i++) {
            int lab[9];
            #pragma unroll
            for (int r = 0; r < 3; r++) {
                lab[r * 3 + 0] = w6[r][i];
                lab[r * 3 + 1] = w6[r][i + 1];
                lab[r * 3 + 2] = w6[r][i + 2];
            }
            wgt[i] = weight_lut(boundary_m2(lab));
        }

        int t0 = w6[1][1], t1 = w6[1][2], t2 = w6[1][3], t3 = w6[1][4];

        // ---- sum of exp over C classes; streaming loads so the 168MB pass
        //      doesn't thrash L2 (keeps targets + gather lines resident) ----
        const float* p = logits + ((long long)(b * C)) * HW + y * W + x4;
        float4 s = make_float4(0.f, 0.f, 0.f, 0.f);
        #pragma unroll
        for (int c = 0; c < C; c++) {
            float4 v = __ldcs((const float4*)(p + c * HW));
            s.x += __expf(v.x);
            s.y += __expf(v.y);
            s.z += __expf(v.z);
            s.w += __expf(v.w);
        }
        // target logits: cached gather
        float vt0 = __ldg(p + t0 * HW + 0);
        float vt1 = __ldg(p + t1 * HW + 1);
        float vt2 = __ldg(p + t2 * HW + 2);
        float vt3 = __ldg(p + t3 * HW + 3);

        val += (__logf(s.x) - vt0) * wgt[0]
             + (__logf(s.y) - vt1) * wgt[1]
             + (__logf(s.z) - vt2) * wgt[2]
             + (__logf(s.w) - vt3) * wgt[3];
    }

    // ---- single block reduction -> per-block partial ----
    float sum = val;
    #pragma unroll
    for (int o = 16; o > 0; o >>= 1)
        sum += __shfl_down_sync(0xffffffffu, sum, o);
    __shared__ double ws[8];
    int warp = threadIdx.x >> 5;
    if ((threadIdx.x & 31) == 0) ws[warp] = (double)sum;
    __syncthreads();

    __shared__ bool is_last;
    if (threadIdx.x == 0) {
        double t = 0.0;
        int nw = blockDim.x >> 5;
        for (int i = 0; i < nw; i++) t += ws[i];
        g_part[blockIdx.x] = t;
        __threadfence();
        unsigned int c = atomicAdd(&g_count, 1u);
        is_last = (c == gridDim.x - 1);
    }
    __syncthreads();

    // ---- last block reduces all partials (L2-resident) and writes output ----
    if (is_last) {
        double s2 = 0.0;
        for (int i = threadIdx.x; i < gridDim.x; i += blockDim.x)
            s2 += g_part[i];
        #pragma unroll
        for (int o = 16; o > 0; o >>= 1)
            s2 += __shfl_down_sync(0xffffffffu, s2, o);
        __shared__ double ws2[8];
        if ((threadIdx.x & 31) == 0) ws2[threadIdx.x >> 5] = s2;
        __syncthreads();
        if (threadIdx.x == 0) {
            double t = 0.0;
            int nw = blockDim.x >> 5;
            for (int i = 0; i < nw; i++) t += ws2[i];
            out[0] = (float)(t * inv_n);
            g_count = 0;          // reset for next graph replay
        }
    }
}

// Generic fallback (scalar, online logsumexp with max).
__global__ __launch_bounds__(256)
void boundary_loss_generic(const float* __restrict__ logits,
                           const int*   __restrict__ targets,
                           int B, int C, int H, int W) {
    const int N  = B * H * W;
    const int HW = H * W;
    int idx = blockIdx.x * blockDim.x + threadIdx.x;

    float val = 0.0f;
    if (idx < N) {
        int x = idx % W;
        int y = (idx / W) % H;
        int b = idx / HW;

        int lab[9];
        #pragma unroll
        for (int dy = -1; dy <= 1; dy++) {
            int yy = min(max(y + dy, 0), H - 1);
            #pragma unroll
            for (int dx = -1; dx <= 1; dx++) {
                int xx = min(max(x + dx, 0), W - 1);
                lab[(dy + 1) * 3 + (dx + 1)] = targets[(b * H + yy) * W + xx];
            }
        }
        float wgt = weight_lut(boundary_m2(lab));

        const float* p = logits + ((long long)b * C * H + y) * W + x;
        float m = -INFINITY, s = 0.0f;
        for (int c = 0; c < C; c++) {
            float vv = p[(long long)c * HW];
            float nm = fmaxf(m, vv);
            s = s * __expf(m - nm) + __expf(vv - nm);
            m = nm;
        }
        float vtg = p[(long long)lab[4] * HW];
        val = ((m + __logf(s)) - vtg) * wgt;
    }

    float sum = val;
    #pragma unroll
    for (int o = 16; o > 0; o >>= 1)
        sum += __shfl_down_sync(0xffffffffu, sum, o);
    __shared__ double ws[8];
    int warp = threadIdx.x >> 5;
    if ((threadIdx.x & 31) == 0) ws[warp] = (double)sum;
    __syncthreads();
    if (threadIdx.x == 0) {
        double t = 0.0;
        int nw = blockDim.x >> 5;
        for (int i = 0; i < nw; i++) t += ws[i];
        atomicAdd(&g_acc, t);
    }
}

extern "C" void kernel_launch(void* const* d_in, const int* in_sizes, int n_in,
                              void* d_out, int out_size) {
    const float* logits  = (const float*)d_in[0];
    const int*   targets = (const int*)d_in[1];
    float*       out     = (float*)d_out;

    const int n_logits = in_sizes[0];
    const int n_pix    = in_sizes[1];
    const int C = n_logits / n_pix;

    const int H = 512, W = 512;
    const int B = n_pix / (H * W);
    const int N = B * H * W;

    if (C == 20 && (n_pix % (H * W)) == 0) {
        const int threads = 256;
        const int Nq = N / 4;
        int blocks = NUM_SMS * BLOCKS_PER_SM;              // one wave, persistent
        const int chunks = (Nq + threads - 1) / threads;
        if (blocks > chunks) blocks = chunks;
        boundary_loss_fused_kernel<20, 512, 512><<<blocks, threads>>>(
            logits, targets, out, B, 1.0 / (double)N);
    } else {
        zero_acc_kernel<<<1, 1>>>();
        const int threads = 256;
        const int blocks = (N + threads - 1) / threads;
        boundary_loss_generic<<<blocks, threads>>>(logits, targets, B, C, H, W);
        finalize_acc_kernel<<<1, 1>>>(out, 1.0 / (double)N);
    }
}

// round 14
// speedup vs baseline: 1.1187x; 1.1187x over previous
#include <cuda_runtime.h>
#include <math.h>

// BoundaryLoss fully-fused kernel: 4 pixels/thread, early-exit Sobel
// (saturating weight => stop when m2>=3; +/-2-coefficient candidates first),
// compile-time H/W/C, streaming (__ldcs) logit loop + cached target gather,
// last-block-done reduction.
// inputs: d_in[0] = logits (B,C,H,W) float32, d_in[1] = targets (B,H,W) int32
// output: scalar float32 mean of (nll * boundary_weight)

#define MAX_BLOCKS 8192
__device__ double g_part[MAX_BLOCKS];
__device__ unsigned int g_count = 0;
__device__ double g_acc;   // generic fallback path

__global__ void zero_acc_kernel() { g_acc = 0.0; }
__global__ void finalize_acc_kernel(float* out, double inv_n) {
    out[0] = (float)(g_acc * inv_n);
}

// weight = exp(clip(sqrt(m2)*3, 0, 5)); integer m2 saturates at 3 =>
// only 4 distinct values.
__device__ __forceinline__ float weight_lut(int m2) {
    // exp(3)=20.0855370, exp(3*sqrt(2))=69.5913868, exp(5)=148.4131591
    return (m2 == 0) ? 1.0f
         : (m2 == 1) ? 20.0855370f
         : (m2 == 2) ? 69.5913868f
                     : 148.4131591f;
}

// max over candidate classes of gx^2+gy^2 for one 3x3 window, with early
// exit once the weight saturates (m2 >= 3). Candidates ordered so the
// +/-2-coefficient cells (which give m2 >= 4 when their class is unique)
// are tested first; center skipped (zero Sobel coefficient).
__device__ __forceinline__ int boundary_m2(const int lab[9]) {
    // sobel_x = [-1 0 1; -2 0 2; -1 0 1], sobel_y = [-1 -2 -1; 0 0 0; 1 2 1]
    const int order[8] = {1, 3, 5, 7, 0, 2, 6, 8};
    int maxm2 = 0;
    #pragma unroll
    for (int ii = 0; ii < 8; ii++) {
        int i = order[ii];
        int c = lab[i];
        int gx = (lab[2] == c) + (lab[8] == c) - (lab[0] == c) - (lab[6] == c)
               + 2 * ((lab[5] == c) - (lab[3] == c));
        int gy = (lab[6] == c) + (lab[8] == c) - (lab[0] == c) - (lab[2] == c)
               + 2 * ((lab[7] == c) - (lab[1] == c));
        maxm2 = max(maxm2, gx * gx + gy * gy);
        if (maxm2 >= 3) return maxm2;   // weight saturated
    }
    return maxm2;
}

template <int C, int H, int W>
__global__ __launch_bounds__(256, 5)
void boundary_loss_fused_kernel(const float* __restrict__ logits,
                                const int*   __restrict__ targets,
                                float* __restrict__ out,
                                int B, double inv_n) {
    constexpr int HW = H * W;
    constexpr int W4 = W >> 2;             // float4 groups per row
    const int Nq = B * H * W4;             // total quads
    int idx = blockIdx.x * blockDim.x + threadIdx.x;

    float val = 0.0f;
    if (idx < Nq) {
        int q  = idx % W4;
        int y  = (idx / W4) % H;
        int b  = idx / (W4 * H);
        int x4 = q << 2;

        // ---- label window: 3 rows x 6 cols (x4-1 .. x4+4), replicate padding ----
        int w6[3][6];
        #pragma unroll
        for (int r = 0; r < 3; r++) {
            int yy = min(max(y + r - 1, 0), H - 1);
            const int* trow = targets + (b * H + yy) * W;
            int4 c4 = __ldg((const int4*)(trow + x4));
            w6[r][1] = c4.x; w6[r][2] = c4.y; w6[r][3] = c4.z; w6[r][4] = c4.w;
            w6[r][0] = __ldg(trow + max(x4 - 1, 0));
            w6[r][5] = __ldg(trow + min(x4 + 4, W - 1));
        }

        // ---- boundary weights for the 4 pixels ----
        float wgt[4];
        #pragma unroll
        for (int i = 0; i < 4; i++) {
            int lab[9];
            #pragma unroll
            for (int r = 0; r < 3; r++) {
                lab[r * 3 + 0] = w6[r][i];
                lab[r * 3 + 1] = w6[r][i + 1];
                lab[r * 3 + 2] = w6[r][i + 2];
            }
            wgt[i] = weight_lut(boundary_m2(lab));
        }

        int t0 = w6[1][1], t1 = w6[1][2], t2 = w6[1][3], t3 = w6[1][4];

        // ---- sum of exp over C classes; streaming loads so the 168MB pass
        //      doesn't thrash L2 (keeps targets + gather lines resident) ----
        const float* p = logits + ((long long)(b * C)) * HW + y * W + x4;
        float4 s = make_float4(0.f, 0.f, 0.f, 0.f);
        #pragma unroll
        for (int c = 0; c < C; c++) {
            float4 v = __ldcs((const float4*)(p + c * HW));
            s.x += __expf(v.x);
            s.y += __expf(v.y);
            s.z += __expf(v.z);
            s.w += __expf(v.w);
        }
        // target logits: cached gather
        float vt0 = __ldg(p + t0 * HW + 0);
        float vt1 = __ldg(p + t1 * HW + 1);
        float vt2 = __ldg(p + t2 * HW + 2);
        float vt3 = __ldg(p + t3 * HW + 3);

        val = (__logf(s.x) - vt0) * wgt[0]
            + (__logf(s.y) - vt1) * wgt[1]
            + (__logf(s.z) - vt2) * wgt[2]
            + (__logf(s.w) - vt3) * wgt[3];
    }

    // ---- block reduction -> per-block partial ----
    float sum = val;
    #pragma unroll
    for (int o = 16; o > 0; o >>= 1)
        sum += __shfl_down_sync(0xffffffffu, sum, o);
    __shared__ double ws[8];
    int warp = threadIdx.x >> 5;
    if ((threadIdx.x & 31) == 0) ws[warp] = (double)sum;
    __syncthreads();

    __shared__ bool is_last;
    if (threadIdx.x == 0) {
        double t = 0.0;
        int nw = blockDim.x >> 5;
        for (int i = 0; i < nw; i++) t += ws[i];
        g_part[blockIdx.x] = t;
        __threadfence();
        unsigned int c = atomicAdd(&g_count, 1u);
        is_last = (c == gridDim.x - 1);
    }
    __syncthreads();

    // ---- last block reduces all partials (L2-resident) and writes output ----
    if (is_last) {
        double s2 = 0.0;
        for (int i = threadIdx.x; i < gridDim.x; i += blockDim.x)
            s2 += g_part[i];
        #pragma unroll
        for (int o = 16; o > 0; o >>= 1)
            s2 += __shfl_down_sync(0xffffffffu, s2, o);
        __shared__ double ws2[8];
        if ((threadIdx.x & 31) == 0) ws2[threadIdx.x >> 5] = s2;
        __syncthreads();
        if (threadIdx.x == 0) {
            double t = 0.0;
            int nw = blockDim.x >> 5;
            for (int i = 0; i < nw; i++) t += ws2[i];
            out[0] = (float)(t * inv_n);
            g_count = 0;          // reset for next graph replay
        }
    }
}

// Generic fallback (scalar, online logsumexp with max).
__global__ __launch_bounds__(256)
void boundary_loss_generic(const float* __restrict__ logits,
                           const int*   __restrict__ targets,
                           int B, int C, int H, int W) {
    const int N  = B * H * W;
    const int HW = H * W;
    int idx = blockIdx.x * blockDim.x + threadIdx.x;

    float val = 0.0f;
    if (idx < N) {
        int x = idx % W;
        int y = (idx / W) % H;
        int b = idx / HW;

        int lab[9];
        #pragma unroll
        for (int dy = -1; dy <= 1; dy++) {
            int yy = min(max(y + dy, 0), H - 1);
            #pragma unroll
            for (int dx = -1; dx <= 1; dx++) {
                int xx = min(max(x + dx, 0), W - 1);
                lab[(dy + 1) * 3 + (dx + 1)] = targets[(b * H + yy) * W + xx];
            }
        }
        float wgt = weight_lut(boundary_m2(lab));

        const float* p = logits + ((long long)b * C * H + y) * W + x;
        float m = -INFINITY, s = 0.0f;
        for (int c = 0; c < C; c++) {
            float vv = p[(long long)c * HW];
            float nm = fmaxf(m, vv);
            s = s * __expf(m - nm) + __expf(vv - nm);
            m = nm;
        }
        float vtg = p[(long long)lab[4] * HW];
        val = ((m + __logf(s)) - vtg) * wgt;
    }

    float sum = val;
    #pragma unroll
    for (int o = 16; o > 0; o >>= 1)
        sum += __shfl_down_sync(0xffffffffu, sum, o);
    __shared__ double ws[8];
    int warp = threadIdx.x >> 5;
    if ((threadIdx.x & 31) == 0) ws[warp] = (double)sum;
    __syncthreads();
    if (threadIdx.x == 0) {
        double t = 0.0;
        int nw = blockDim.x >> 5;
        for (int i = 0; i < nw; i++) t += ws[i];
        atomicAdd(&g_acc, t);
    }
}

extern "C" void kernel_launch(void* const* d_in, const int* in_sizes, int n_in,
                              void* d_out, int out_size) {
    const float* logits  = (const float*)d_in[0];
    const int*   targets = (const int*)d_in[1];
    float*       out     = (float*)d_out;

    const int n_logits = in_sizes[0];
    const int n_pix    = in_sizes[1];
    const int C = n_logits / n_pix;

    const int H = 512, W = 512;
    const int B = n_pix / (H * W);
    const int N = B * H * W;

    if (C == 20 && (n_pix % (H * W)) == 0) {
        const int threads = 256;
        const int Nq = N / 4;
        const int blocks = (Nq + threads - 1) / threads;   // 2048 for B=8
        boundary_loss_fused_kernel<20, 512, 512><<<blocks, threads>>>(
            logits, targets, out, B, 1.0 / (double)N);
    } else {
        zero_acc_kernel<<<1, 1>>>();
        const int threads = 256;
        const int blocks = (N + threads - 1) / threads;
        boundary_loss_generic<<<blocks, threads>>>(logits, targets, B, C, H, W);
        finalize_acc_kernel<<<1, 1>>>(out, 1.0 / (double)N);
    }
}